// round 10
// baseline (speedup 1.0000x reference)
#include <cuda_runtime.h>
#include <math.h>

#define NSTEPS 8192
#define NNODES 4096
#define SG 256
#define NROW 2048
#define DFF 2048
#define H1DIM 512

// h_t for every step (consumed by the sampler kernel)
__device__ float g_h_all[NSTEPS * SG];
// folded matrices (recomputed deterministically every launch)
__device__ float g_A[SG * SG];       // Wo @ Wv
__device__ float g_Bm[SG * SG];      // (I + A) @ Wg
__device__ float g_d[SG];            // (I+A)@bg + Wo@bv + bo
__device__ float g_C[SG * H1DIM];    // Bm @ W2
__device__ float g_e[SG];            // Bm @ b2 + d
// LN1 fold: Wf1g = Wf1*diag(ln1g), Rff = rowsum, c1 = Wf1@ln1b + bf1
__device__ float g_wf1g[DFF * SG];
__device__ float g_Rff[DFF];
__device__ float g_c1[DFF];
// LN2 fold into W1 g-columns
__device__ float g_w1gg[H1DIM * SG];
__device__ float g_R1[H1DIM];
__device__ float g_k1[H1DIM];
// cross-CTA partial buffers, TRANSPOSED: [entry][rank] so consumers read
// 16 contiguous floats (4x float4) per entry.
__device__ __align__(16) float g_p1t[SG * 16];
__device__ __align__(16) float g_pht[SG * 16];
__device__ __align__(16) float g_p2t[SG * 16];
// fallback broadcast buffers
__device__ float g_bh1[H1DIM];
__device__ float g_by1[SG];
__device__ float g_bff[DFF];
__device__ float g_by2[SG];

#define CLU_SYNC()                                                        \
    do {                                                                  \
        asm volatile("barrier.cluster.arrive.aligned;" ::: "memory");    \
        asm volatile("barrier.cluster.wait.aligned;" ::: "memory");      \
    } while (0)

__device__ __forceinline__ unsigned smem_u32(const void* p) {
    return (unsigned)__cvta_generic_to_shared(p);
}

__device__ __forceinline__ void arrive_remote_rel(unsigned lmbar, unsigned rank) {
    unsigned r;
    asm volatile("mapa.shared::cluster.u32 %0, %1, %2;" : "=r"(r) : "r"(lmbar), "r"(rank));
    asm volatile("mbarrier.arrive.release.cluster.shared::cluster.b64 _, [%0];"
                 :: "r"(r) : "memory");
}

__device__ __forceinline__ void bar_wait_acq(unsigned mbar, unsigned parity) {
    asm volatile(
        "{\n\t.reg .pred P;\n\t"
        "WL%=:\n\t"
        "mbarrier.try_wait.parity.acquire.cluster.shared::cta.b64 P, [%0], %1, 0x989680;\n\t"
        "@P bra WD%=;\n\t"
        "bra WL%=;\n\t"
        "WD%=:\n\t}"
        :: "r"(mbar), "r"(parity) : "memory");
}

__device__ __forceinline__ float warp_reduce(float v) {
#pragma unroll
    for (int o = 16; o; o >>= 1) v += __shfl_xor_sync(0xffffffffu, v, o);
    return v;
}

template <int C>
__device__ __forceinline__ float row_dot(const float* __restrict__ W,
                                         const float* __restrict__ x, int lane) {
    const float4* __restrict__ W4 = reinterpret_cast<const float4*>(W);
    const float4* __restrict__ x4 = reinterpret_cast<const float4*>(x);
    float s = 0.f;
#pragma unroll
    for (int c = 0; c < C / 4; c += 32) {
        float4 w = W4[c + lane];
        float4 xv = x4[c + lane];
        s += w.x * xv.x + w.y * xv.y + w.z * xv.z + w.w * xv.w;
    }
    return warp_reduce(s);
}

// ordered sum of 16 transposed partials (bit-identical to k=0..15 loop)
__device__ __forceinline__ float sum16(const float* __restrict__ base, float s) {
    const float4* p = reinterpret_cast<const float4*>(base);
    float4 v0 = p[0], v1 = p[1], v2 = p[2], v3 = p[3];
    s += v0.x; s += v0.y; s += v0.z; s += v0.w;
    s += v1.x; s += v1.y; s += v1.z; s += v1.w;
    s += v2.x; s += v2.y; s += v2.z; s += v2.w;
    s += v3.x; s += v3.y; s += v3.z; s += v3.w;
    return s;
}

// two-pass LN (fallback kernel only)
__device__ __forceinline__ void layernorm256(const float* __restrict__ y,
                                             float* __restrict__ out,
                                             const float* __restrict__ gma,
                                             const float* __restrict__ bta,
                                             int tid, float* red) {
    int w = tid >> 5, lane = tid & 31;
    if (w == 0) {
        float s = 0.f;
#pragma unroll
        for (int i = 0; i < 8; ++i) s += y[lane + 32 * i];
        s = warp_reduce(s);
        if (lane == 0) red[0] = s * (1.f / 256.f);
    }
    __syncthreads();
    float mu = red[0];
    if (w == 0) {
        float s = 0.f;
#pragma unroll
        for (int i = 0; i < 8; ++i) {
            float d = y[lane + 32 * i] - mu;
            s += d * d;
        }
        s = warp_reduce(s);
        if (lane == 0) red[1] = 1.f / sqrtf(s * (1.f / 256.f) + 1e-5f);
    }
    __syncthreads();
    float inv = red[1];
    if (tid < 256) out[tid] = (y[tid] - mu) * inv * gma[tid] + bta[tid];
    __syncthreads();
}

// ---------------------------------------------------------------------------
// Setup kernels
// ---------------------------------------------------------------------------
__global__ void fold1(const float* __restrict__ Wo, const float* __restrict__ Wv) {
    int i = blockIdx.x, j = threadIdx.x;
    float s = 0.f;
    for (int k = 0; k < SG; ++k) s += Wo[i * SG + k] * Wv[k * SG + j];
    g_A[i * SG + j] = s;
}

__global__ void fold2(const float* __restrict__ Wg, const float* __restrict__ bg,
                      const float* __restrict__ Wo, const float* __restrict__ bv,
                      const float* __restrict__ bo) {
    int i = blockIdx.x, j = threadIdx.x;
    float s = Wg[i * SG + j];
    for (int k = 0; k < SG; ++k) s += g_A[i * SG + k] * Wg[k * SG + j];
    g_Bm[i * SG + j] = s;
    if (j == 0) {
        float t = bg[i] + bo[i];
        for (int k = 0; k < SG; ++k) t += g_A[i * SG + k] * bg[k];
        for (int k = 0; k < SG; ++k) t += Wo[i * SG + k] * bv[k];
        g_d[i] = t;
    }
}

__global__ void fold3(const float* __restrict__ W2, const float* __restrict__ b2) {
    int i = blockIdx.x, j = threadIdx.x;
    float s = 0.f;
    for (int k = 0; k < SG; ++k) s += g_Bm[i * SG + k] * W2[k * H1DIM + j];
    g_C[i * H1DIM + j] = s;
    if (j == 0) {
        float t = g_d[i];
        for (int k = 0; k < SG; ++k) t += g_Bm[i * SG + k] * b2[k];
        g_e[i] = t;
    }
}

__global__ void fold4(const float* __restrict__ Wf1, const float* __restrict__ bf1,
                      const float* __restrict__ ln1g, const float* __restrict__ ln1b) {
    int r = blockIdx.x, j = threadIdx.x;
    __shared__ float s1[SG], s2[SG];
    float wv = Wf1[(size_t)r * SG + j];
    float wg = wv * ln1g[j];
    g_wf1g[(size_t)r * SG + j] = wg;
    s1[j] = wg;
    s2[j] = wv * ln1b[j];
    __syncthreads();
    for (int o = 128; o; o >>= 1) {
        if (j < o) { s1[j] += s1[j + o]; s2[j] += s2[j + o]; }
        __syncthreads();
    }
    if (j == 0) { g_Rff[r] = s1[0]; g_c1[r] = s2[0] + bf1[r]; }
}

__global__ void fold5(const float* __restrict__ W1, const float* __restrict__ b1,
                      const float* __restrict__ ln2g, const float* __restrict__ ln2b) {
    int r = blockIdx.x, j = threadIdx.x;
    __shared__ float s1[SG], s2[SG];
    float wv = W1[(size_t)r * H1DIM + 256 + j];
    float wg = wv * ln2g[j];
    g_w1gg[(size_t)r * SG + j] = wg;
    s1[j] = wg;
    s2[j] = wv * ln2b[j];
    __syncthreads();
    for (int o = 128; o; o >>= 1) {
        if (j < o) { s1[j] += s1[j + o]; s2[j] += s2[j + o]; }
        __syncthreads();
    }
    if (j == 0) { g_R1[r] = s1[0]; g_k1[r] = s2[0] + b1[r]; }
}

// ---------------------------------------------------------------------------
// Main chain: 16-CTA cluster, 512 thr/CTA, 2 mbarrier syncs/step.
// ---------------------------------------------------------------------------
#define SEQ5_SMEM_FLOATS (32 * SG + 32 * SG + 128 * SG + SG + SG + SG + 32 + 128 + 512 + 128 + 128 + 32)
#define SEQ5_SMEM_BYTES (SEQ5_SMEM_FLOATS * 4)

__global__ void __launch_bounds__(512, 1) seq5_kernel(
    const float* __restrict__ gnn,
    const float* __restrict__ W1, const float* __restrict__ b1,
    const float* __restrict__ W2, const float* __restrict__ b2,
    const float* __restrict__ Wf2, const float* __restrict__ bf2,
    const float* __restrict__ ln1g, const float* __restrict__ ln1b) {
    extern __shared__ __align__(16) float sm[];
    float* w1ms  = sm;                  // [32][256]  W1 m-columns slice
    float* w1gs  = w1ms + 32 * SG;      // [32][256]  W1gg slice
    float* wf1s  = w1gs + 32 * SG;      // [128][256] Wf1g slice
    float* mbuf  = wf1s + 128 * SG;     // 256
    float* y1s   = mbuf + SG;           // 256
    float* y2s   = y1s + SG;            // 256 (raw y2)
    float* h1loc = y2s + SG;            // 32
    float* ffloc = h1loc + 32;          // 128
    float* p2tmp = ffloc + 128;         // 512
    float* rffs  = p2tmp + 512;         // 128
    float* c1s   = rffs + 128;          // 128
    float* redsm = c1s + 128;           // 32
    __shared__ __align__(8) unsigned long long mb[2];

    int tid = threadIdx.x, w = tid >> 5, lane = tid & 31;
    unsigned rank;
    asm("mov.u32 %0, %%cluster_ctarank;" : "=r"(rank));
    unsigned a_mb = smem_u32(mb);

    // resident smem weights
    for (int i = tid; i < 32 * SG; i += 512) {
        int r = i >> 8, j = i & 255;
        w1ms[i] = W1[(size_t)(rank * 32 + r) * H1DIM + j];
        w1gs[i] = g_w1gg[(size_t)(rank * 32 + r) * SG + j];
    }
    for (int i = tid; i < 128 * SG; i += 512)
        wf1s[i] = g_wf1g[(size_t)rank * 128 * SG + i];
    if (tid < 128) {
        rffs[tid] = g_Rff[rank * 128 + tid];
        c1s[tid]  = g_c1[rank * 128 + tid];
    }

    // persistent register weights
    float pw[32];
    {
        const float* psrc = (tid < 256)
            ? (W2 + (size_t)tid * H1DIM + rank * 32)
            : (g_C + (size_t)(tid - 256) * H1DIM + rank * 32);
#pragma unroll
        for (int c = 0; c < 32; ++c) pw[c] = psrc[c];
    }
    float wf2c[64];
    {
        int r2 = tid & 255, half = tid >> 8;
        const float* wsrc = Wf2 + (size_t)r2 * DFF + rank * 128 + half * 64;
#pragma unroll
        for (int c = 0; c < 64; ++c) wf2c[c] = wsrc[c];
    }
    const int g1a = rank * 32 + w, g1b = g1a + 16;
    float b1a = b1[g1a], b1b = b1[g1b];
    float R1a = g_R1[g1a], R1b = g_R1[g1b];
    float k1a = g_k1[g1a], k1b = g_k1[g1b];
    float e_r = (tid < 256) ? g_e[tid] : 0.f;
    float bf2_r = (tid < 256) ? bf2[tid] : 0.f;
    float l1g = 0.f, l1b_ = 0.f;
    if (tid < 256) { l1g = ln1g[tid]; l1b_ = ln1b[tid]; }
    float b2row = 0.f;
    int hrow = -1;
    if (tid >= 256 && tid < 256 + 16) {
        hrow = rank * 16 + (tid - 256);
        b2row = b2[hrow];
    }

    if (tid < 2)
        asm volatile("mbarrier.init.shared.b64 [%0], %1;"
                     :: "r"(a_mb + tid * 8), "r"(16) : "memory");
    if (tid < 256) {
        y2s[tid] = 0.f;
        mbuf[tid] = gnn[(size_t)tid];  // m_0
    }
    __syncthreads();
    CLU_SYNC();

    float md0 = row_dot<SG>(w1ms + w * SG, mbuf, lane);
    float md1 = row_dot<SG>(w1ms + (w + 16) * SG, mbuf, lane);
    float mu1 = 0.f, inv1 = 0.f;

    for (int t = 0; t < NSTEPS; ++t) {
        unsigned par = (unsigned)(t & 1);

        float mnext = 0.f;
        if (tid < 256)
            mnext = gnn[(size_t)((t + 1) & (NNODES - 1)) * SG + tid];

        // S1 g-dot over RAW y2; concurrent y2-stats finalize
        float dg0 = row_dot<SG>(w1gs + w * SG, y2s, lane);
        float dg1 = row_dot<SG>(w1gs + (w + 16) * SG, y2s, lane);
        if (t > 0 && tid == 0) {
            float s = 0.f, s2 = 0.f;
#pragma unroll
            for (int i = 0; i < 8; ++i) { s += redsm[2 * i]; s2 += redsm[2 * i + 1]; }
            float mu = s * (1.f / 256.f);
            float var = s2 * (1.f / 256.f) - mu * mu;
            redsm[16] = mu;
            redsm[17] = 1.f / sqrtf(var + 1e-5f);
        }
        __syncthreads();

        // S1 epilogue -> h1 slice
        {
            float v0, v1;
            if (t == 0) {
                v0 = md0 + b1a;
                v1 = md1 + b1b;
            } else {
                float mu2 = redsm[16], inv2 = redsm[17];
                v0 = md0 + inv2 * (dg0 - mu2 * R1a) + k1a;
                v1 = md1 + inv2 * (dg1 - mu2 * R1b) + k1b;
            }
            if (lane == 0) {
                h1loc[w] = fmaxf(v0, 0.f);
                h1loc[w + 16] = fmaxf(v1, 0.f);
            }
        }
        __syncthreads();

        // p1 partials: float4 h1loc loads, sequential accumulation (c order)
        {
            const float4* h4 = reinterpret_cast<const float4*>(h1loc);
            float acc = 0.f;
#pragma unroll
            for (int c4 = 0; c4 < 8; ++c4) {
                float4 hv = h4[c4];
                acc += pw[4 * c4 + 0] * hv.x;
                acc += pw[4 * c4 + 1] * hv.y;
                acc += pw[4 * c4 + 2] * hv.z;
                acc += pw[4 * c4 + 3] * hv.w;
            }
            if (tid < 256) g_pht[(size_t)tid * 16 + rank] = acc;
            else           g_p1t[(size_t)(tid - 256) * 16 + rank] = acc;
        }
        if (tid < 256) mbuf[tid] = mnext;
        __syncthreads();
        if (tid < 16) arrive_remote_rel(a_mb + 0 * 8, (unsigned)tid);

        // shadow: m-dot for t+1
        md0 = row_dot<SG>(w1ms + w * SG, mbuf, lane);
        md1 = row_dot<SG>(w1ms + (w + 16) * SG, mbuf, lane);

        bar_wait_acq(a_mb + 0 * 8, par);                   // sync 1

        // reduce y1 (+ warp stats); h rows
        float y1v = 0.f;
        if (tid < 256) {
            float s = sum16(g_p1t + (size_t)tid * 16, e_r);
            y1v = s;
            y1s[tid] = s;
            float sa = s, s2a = s * s;
#pragma unroll
            for (int o = 16; o; o >>= 1) {
                sa += __shfl_xor_sync(0xffffffffu, sa, o);
                s2a += __shfl_xor_sync(0xffffffffu, s2a, o);
            }
            if (lane == 0) { redsm[2 * w] = sa; redsm[2 * w + 1] = s2a; }
        } else if (hrow >= 0) {
            float s = sum16(g_pht + (size_t)hrow * 16, b2row);
            g_h_all[(size_t)t * SG + hrow] = s;
        }
        __syncthreads();

        // raw z = Wf1g @ y1 -> ffloc; concurrent LN1 stats finalize
#pragma unroll
        for (int i = 0; i < 8; ++i) {
            float zz = row_dot<SG>(wf1s + (w + 16 * i) * SG, y1s, lane);
            if (lane == 0) ffloc[w + 16 * i] = zz;
        }
        if (tid == 0) {
            float s = 0.f, s2 = 0.f;
#pragma unroll
            for (int i = 0; i < 8; ++i) { s += redsm[2 * i]; s2 += redsm[2 * i + 1]; }
            float mu = s * (1.f / 256.f);
            float var = s2 * (1.f / 256.f) - mu * mu;
            redsm[16] = mu;
            redsm[17] = 1.f / sqrtf(var + 1e-5f);
        }
        __syncthreads();

        mu1 = redsm[16];
        inv1 = redsm[17];
        // ff epilogue in place (LN1 fold), one thread per ff row
        if (tid < 128)
            ffloc[tid] = fmaxf(inv1 * (ffloc[tid] - mu1 * rffs[tid]) + c1s[tid], 0.f);
        __syncthreads();

        // p2 partials: float4 ffloc loads, sequential accumulation
        {
            int half = tid >> 8;
            const float4* fl4 = reinterpret_cast<const float4*>(ffloc + half * 64);
            float a2 = 0.f;
#pragma unroll
            for (int c4 = 0; c4 < 16; ++c4) {
                float4 fv = fl4[c4];
                a2 += wf2c[4 * c4 + 0] * fv.x;
                a2 += wf2c[4 * c4 + 1] * fv.y;
                a2 += wf2c[4 * c4 + 2] * fv.z;
                a2 += wf2c[4 * c4 + 3] * fv.w;
            }
            p2tmp[tid] = a2;
        }
        __syncthreads();
        if (tid < 256) g_p2t[(size_t)tid * 16 + rank] = p2tmp[tid] + p2tmp[tid + 256];
        __syncthreads();
        if (tid < 16) arrive_remote_rel(a_mb + 1 * 8, (unsigned)tid);
        bar_wait_acq(a_mb + 1 * 8, par);                   // sync 2

        // reduce y2 raw + stats
        if (tid < 256) {
            float x = (y1v - mu1) * inv1 * l1g + l1b_;
            float s = sum16(g_p2t + (size_t)tid * 16, x + bf2_r);
            y2s[tid] = s;
            float sa = s, s2a = s * s;
#pragma unroll
            for (int o = 16; o; o >>= 1) {
                sa += __shfl_xor_sync(0xffffffffu, sa, o);
                s2a += __shfl_xor_sync(0xffffffffu, s2a, o);
            }
            if (lane == 0) { redsm[2 * w] = sa; redsm[2 * w + 1] = s2a; }
        }
        __syncthreads();
    }
    CLU_SYNC();
}

// ---------------------------------------------------------------------------
// Fallback (cluster size < 16): R4-proven streaming kernel, CL=8.
// ---------------------------------------------------------------------------
__global__ void __launch_bounds__(1024, 1) seq_fallback8(
    const float* __restrict__ gnn,
    const float* __restrict__ W1, const float* __restrict__ b1,
    const float* __restrict__ W2, const float* __restrict__ b2,
    const float* __restrict__ Wg, const float* __restrict__ bg,
    const float* __restrict__ Wv, const float* __restrict__ bv,
    const float* __restrict__ Wo, const float* __restrict__ bo,
    const float* __restrict__ Wf1, const float* __restrict__ bf1,
    const float* __restrict__ Wf2, const float* __restrict__ bf2,
    const float* __restrict__ ln1g, const float* __restrict__ ln1b,
    const float* __restrict__ ln2g, const float* __restrict__ ln2b) {
    constexpr int CL = 8;
    constexpr int R_H1 = H1DIM / CL, R_SG = SG / CL, R_FF = DFF / CL;
    __shared__ __align__(16) float cat[H1DIM];
    __shared__ __align__(16) float h1s[H1DIM];
    __shared__ __align__(16) float hs[SG];
    __shared__ __align__(16) float gns[SG];
    __shared__ __align__(16) float vvs[SG];
    __shared__ __align__(16) float ys[SG];
    __shared__ __align__(16) float xs[SG];
    __shared__ __align__(16) float ff1s[DFF];
    __shared__ float red[2];

    int tid = threadIdx.x, w = tid >> 5, lane = tid & 31;
    unsigned rank;
    asm("mov.u32 %0, %%cluster_ctarank;" : "=r"(rank));
    if (tid < 256) cat[256 + tid] = 0.f;
    __syncthreads();

    for (int t = 0; t < NSTEPS; ++t) {
        if (tid < 256) cat[tid] = gnn[(size_t)(t & (NNODES - 1)) * SG + tid];
        __syncthreads();
        for (int r = w; r < R_H1; r += 32) {
            int gr = rank * R_H1 + r;
            float s = row_dot<H1DIM>(W1 + (size_t)gr * H1DIM, cat, lane);
            if (lane == 0) g_bh1[gr] = fmaxf(s + b1[gr], 0.f);
        }
        CLU_SYNC();
        for (int i = tid; i < H1DIM; i += 1024) h1s[i] = g_bh1[i];
        __syncthreads();
        float* gh = g_h_all + (size_t)t * SG;
        for (int r = w; r < R_SG; r += 32) {
            int gr = rank * R_SG + r;
            float s = row_dot<H1DIM>(W2 + (size_t)gr * H1DIM, h1s, lane);
            if (lane == 0) gh[gr] = s + b2[gr];
        }
        CLU_SYNC();
        for (int i = tid; i < SG; i += 1024) hs[i] = gh[i];
        __syncthreads();
        for (int r = w; r < R_SG; r += 32) {
            int gr = rank * R_SG + r;
            float s = row_dot<SG>(Wg + (size_t)gr * SG, hs, lane);
            if (lane == 0) g_by1[gr] = s + bg[gr];
        }
        CLU_SYNC();
        for (int i = tid; i < SG; i += 1024) gns[i] = g_by1[i];
        __syncthreads();
        for (int r = w; r < R_SG; r += 32) {
            int gr = rank * R_SG + r;
            float s = row_dot<SG>(Wv + (size_t)gr * SG, gns, lane);
            if (lane == 0) g_by2[gr] = s + bv[gr];
        }
        CLU_SYNC();
        for (int i = tid; i < SG; i += 1024) vvs[i] = g_by2[i];
        __syncthreads();
        for (int r = w; r < R_SG; r += 32) {
            int gr = rank * R_SG + r;
            float s = row_dot<SG>(Wo + (size_t)gr * SG, vvs, lane);
            if (lane == 0) g_by1[gr] = gns[gr] + (s + bo[gr]);
        }
        CLU_SYNC();
        for (int i = tid; i < SG; i += 1024) ys[i] = g_by1[i];
        __syncthreads();
        layernorm256(ys, xs, ln1g, ln1b, tid, red);
        for (int r = w; r < R_FF; r += 32) {
            int gr = rank * R_FF + r;
            float s = row_dot<SG>(Wf1 + (size_t)gr * SG, xs, lane);
            if (lane == 0) g_bff[gr] = fmaxf(s + bf1[gr], 0.f);
        }
        CLU_SYNC();
        for (int i = tid; i < DFF; i += 1024) ff1s[i] = g_bff[i];
        __syncthreads();
        for (int r = w; r < R_SG; r += 32) {
            int gr = rank * R_SG + r;
            float s = row_dot<DFF>(Wf2 + (size_t)gr * DFF, ff1s, lane);
            if (lane == 0) g_by2[gr] = xs[gr] + (s + bf2[gr]);
        }
        CLU_SYNC();
        for (int i = tid; i < SG; i += 1024) ys[i] = g_by2[i];
        __syncthreads();
        layernorm256(ys, cat + 256, ln2g, ln2b, tid, red);
    }
}

// ---------------------------------------------------------------------------
// Sampler: T=16 timesteps per block (halved Wr traffic), bit-exact probs path.
// ---------------------------------------------------------------------------
#define SAMP_T 16
#define SAMP_THREADS 512
#define SAMP_SMEM ((SAMP_T * SG + SAMP_T * NROW) * 4)

__global__ void __launch_bounds__(SAMP_THREADS) sample_kernel16(
    const float* __restrict__ u,
    const float* __restrict__ Wr, const float* __restrict__ br,
    float* __restrict__ out) {
    extern __shared__ __align__(16) float sm[];
    float* hsm = sm;                  // [SAMP_T][SG]
    float* probs = sm + SAMP_T * SG;  // [SAMP_T][NROW]
    __shared__ int cnt[SAMP_T][4];
    __shared__ int sel[SAMP_T];

    int tb = blockIdx.x * SAMP_T;
    int tid = threadIdx.x, w = tid >> 5, lane = tid & 31;

    for (int i = tid; i < SAMP_T * SG; i += SAMP_THREADS)
        hsm[i] = g_h_all[(size_t)tb * SG + i];
    if (tid < SAMP_T * 4) cnt[tid >> 2][tid & 3] = 0;
    __syncthreads();

    for (int r = w; r < NROW; r += 16) {
        const float* Wrow = Wr + (size_t)r * SG;
        float brv = br[r];
#pragma unroll
        for (int j = 0; j < SAMP_T; ++j) {
            float s = row_dot<SG>(Wrow, hsm + j * SG, lane);
            if (lane == 0) {
                float z = s + brv;
                float p;
                if (z >= 0.f) {
                    p = 1.f / (1.f + expf(-z));
                } else {
                    float e = expf(z);
                    p = e / (1.f + e);
                }
                probs[j * NROW + r] = p;
            }
        }
    }
    __syncthreads();

#pragma unroll
    for (int j = 0; j < SAMP_T; ++j) {
        const float* __restrict__ ut = u + (size_t)(tb + j) * 4 * NROW;
        int c[4] = {0, 0, 0, 0};
#pragma unroll
        for (int k = 0; k < 4; ++k)
#pragma unroll
            for (int i = 0; i < NROW / SAMP_THREADS; ++i) {
                int n = tid + SAMP_THREADS * i;
                c[k] += (ut[k * NROW + n] < probs[j * NROW + n]) ? 1 : 0;
            }
#pragma unroll
        for (int k = 0; k < 4; ++k) {
            int s = c[k];
#pragma unroll
            for (int o = 16; o; o >>= 1) s += __shfl_xor_sync(0xffffffffu, s, o);
            if (lane == 0) atomicAdd(&cnt[j][k], s);
        }
    }
    __syncthreads();

    if (tid < SAMP_T) {
        int idx = 0;
        for (int k = 3; k >= 0; --k) {
            int ck = cnt[tid][k];
            bool valid = (ck == 0) || (ck >= 2 && ck <= 6);
            if (valid) idx = k;
        }
        sel[tid] = idx;
    }
    __syncthreads();

#pragma unroll
    for (int j = 0; j < SAMP_T; ++j) {
        const float* __restrict__ ut = u + (size_t)(tb + j) * 4 * NROW;
        int idx = sel[j];
#pragma unroll
        for (int i = 0; i < NROW / SAMP_THREADS; ++i) {
            int n = tid + SAMP_THREADS * i;
            out[(size_t)(tb + j) * NROW + n] =
                (ut[idx * NROW + n] < probs[j * NROW + n]) ? 1.f : 0.f;
        }
    }
}

extern "C" void kernel_launch(void* const* d_in, const int* in_sizes, int n_in,
                              void* d_out, int out_size) {
    (void)in_sizes; (void)n_in; (void)out_size;
    const float* gnn  = (const float*)d_in[0];
    const float* u    = (const float*)d_in[2];
    const float* W1   = (const float*)d_in[3];
    const float* b1   = (const float*)d_in[4];
    const float* W2   = (const float*)d_in[5];
    const float* b2   = (const float*)d_in[6];
    const float* Wr   = (const float*)d_in[7];
    const float* br   = (const float*)d_in[8];
    const float* Wg   = (const float*)d_in[9];
    const float* bg   = (const float*)d_in[10];
    const float* Wv   = (const float*)d_in[11];
    const float* bv   = (const float*)d_in[12];
    const float* Wo   = (const float*)d_in[13];
    const float* bo   = (const float*)d_in[14];
    const float* Wf1  = (const float*)d_in[15];
    const float* bf1  = (const float*)d_in[16];
    const float* Wf2  = (const float*)d_in[17];
    const float* bf2  = (const float*)d_in[18];
    const float* ln1g = (const float*)d_in[19];
    const float* ln1b = (const float*)d_in[20];
    const float* ln2g = (const float*)d_in[21];
    const float* ln2b = (const float*)d_in[22];

    // folds (deterministic, every call)
    fold1<<<SG, SG>>>(Wo, Wv);
    fold2<<<SG, SG>>>(Wg, bg, Wo, bv, bo);
    fold3<<<SG, H1DIM>>>(W2, b2);
    fold4<<<DFF, SG>>>(Wf1, bf1, ln1g, ln1b);
    fold5<<<H1DIM, SG>>>(W1, b1, ln2g, ln2b);

    cudaFuncSetAttribute(seq5_kernel,
                         cudaFuncAttributeMaxDynamicSharedMemorySize, SEQ5_SMEM_BYTES);
    cudaFuncSetAttribute(seq5_kernel,
                         cudaFuncAttributeNonPortableClusterSizeAllowed, 1);

    cudaError_t e = cudaErrorUnknown;
    {
        cudaLaunchConfig_t cfg = {};
        cfg.gridDim = dim3(16, 1, 1);
        cfg.blockDim = dim3(512, 1, 1);
        cfg.dynamicSmemBytes = SEQ5_SMEM_BYTES;
        cfg.stream = 0;
        cudaLaunchAttribute at[1];
        at[0].id = cudaLaunchAttributeClusterDimension;
        at[0].val.clusterDim.x = 16;
        at[0].val.clusterDim.y = 1;
        at[0].val.clusterDim.z = 1;
        cfg.attrs = at;
        cfg.numAttrs = 1;
        e = cudaLaunchKernelEx(&cfg, seq5_kernel,
                               gnn, W1, b1, W2, b2, Wf2, bf2, ln1g, ln1b);
    }
    if (e != cudaSuccess) {
        cudaLaunchConfig_t cfg = {};
        cfg.gridDim = dim3(8, 1, 1);
        cfg.blockDim = dim3(1024, 1, 1);
        cfg.dynamicSmemBytes = 0;
        cfg.stream = 0;
        cudaLaunchAttribute at[1];
        at[0].id = cudaLaunchAttributeClusterDimension;
        at[0].val.clusterDim.x = 8;
        at[0].val.clusterDim.y = 1;
        at[0].val.clusterDim.z = 1;
        cfg.attrs = at;
        cfg.numAttrs = 1;
        cudaLaunchKernelEx(&cfg, seq_fallback8,
                           gnn, W1, b1, W2, b2, Wg, bg, Wv, bv, Wo, bo,
                           Wf1, bf1, Wf2, bf2, ln1g, ln1b, ln2g, ln2b);
    }

    cudaFuncSetAttribute(sample_kernel16,
                         cudaFuncAttributeMaxDynamicSharedMemorySize, SAMP_SMEM);
    sample_kernel16<<<NSTEPS / SAMP_T, SAMP_THREADS, SAMP_SMEM>>>(
        u, Wr, br, (float*)d_out);
}

// round 11
// speedup vs baseline: 1.1539x; 1.1539x over previous
#include <cuda_runtime.h>
#include <math.h>

#define NSTEPS 8192
#define NNODES 4096
#define SG 256
#define NROW 2048
#define DFF 2048
#define H1DIM 512

// h_t for every step (consumed by the sampler kernel)
__device__ float g_h_all[NSTEPS * SG];
// folded matrices (recomputed deterministically every launch)
__device__ float g_A[SG * SG];       // Wo @ Wv
__device__ float g_Bm[SG * SG];      // (I + A) @ Wg
__device__ float g_d[SG];            // (I+A)@bg + Wo@bv + bo
__device__ float g_C[SG * H1DIM];    // Bm @ W2
__device__ float g_e[SG];            // Bm @ b2 + d
// LN1 fold: Wf1g = Wf1*diag(ln1g), Rff = rowsum, c1 = Wf1@ln1b + bf1
__device__ float g_wf1g[DFF * SG];
__device__ float g_Rff[DFF];
__device__ float g_c1[DFF];
// LN2 fold into W1 g-columns
__device__ float g_w1gg[H1DIM * SG];
__device__ float g_R1[H1DIM];
__device__ float g_k1[H1DIM];
// cross-CTA partial buffers (L2-resident), COALESCED writes: [rank][entry]
__device__ float g_p1[16 * SG];      // y1 partials
__device__ float g_ph[16 * SG];      // h partials
__device__ float g_p2[16 * SG];      // y2 partials
// fallback broadcast buffers
__device__ float g_bh1[H1DIM];
__device__ float g_by1[SG];
__device__ float g_bff[DFF];
__device__ float g_by2[SG];

#define CLU_SYNC()                                                        \
    do {                                                                  \
        asm volatile("barrier.cluster.arrive.aligned;" ::: "memory");    \
        asm volatile("barrier.cluster.wait.aligned;" ::: "memory");      \
    } while (0)

__device__ __forceinline__ unsigned smem_u32(const void* p) {
    return (unsigned)__cvta_generic_to_shared(p);
}

__device__ __forceinline__ void arrive_remote_rel(unsigned lmbar, unsigned rank) {
    unsigned r;
    asm volatile("mapa.shared::cluster.u32 %0, %1, %2;" : "=r"(r) : "r"(lmbar), "r"(rank));
    asm volatile("mbarrier.arrive.release.cluster.shared::cluster.b64 _, [%0];"
                 :: "r"(r) : "memory");
}

__device__ __forceinline__ void bar_wait_acq(unsigned mbar, unsigned parity) {
    asm volatile(
        "{\n\t.reg .pred P;\n\t"
        "WL%=:\n\t"
        "mbarrier.try_wait.parity.acquire.cluster.shared::cta.b64 P, [%0], %1, 0x989680;\n\t"
        "@P bra WD%=;\n\t"
        "bra WL%=;\n\t"
        "WD%=:\n\t}"
        :: "r"(mbar), "r"(parity) : "memory");
}

__device__ __forceinline__ float warp_reduce(float v) {
#pragma unroll
    for (int o = 16; o; o >>= 1) v += __shfl_xor_sync(0xffffffffu, v, o);
    return v;
}

template <int C>
__device__ __forceinline__ float row_dot(const float* __restrict__ W,
                                         const float* __restrict__ x, int lane) {
    const float4* __restrict__ W4 = reinterpret_cast<const float4*>(W);
    const float4* __restrict__ x4 = reinterpret_cast<const float4*>(x);
    float s = 0.f;
#pragma unroll
    for (int c = 0; c < C / 4; c += 32) {
        float4 w = W4[c + lane];
        float4 xv = x4[c + lane];
        s += w.x * xv.x + w.y * xv.y + w.z * xv.z + w.w * xv.w;
    }
    return warp_reduce(s);
}

// two-pass LN (fallback kernel only)
__device__ __forceinline__ void layernorm256(const float* __restrict__ y,
                                             float* __restrict__ out,
                                             const float* __restrict__ gma,
                                             const float* __restrict__ bta,
                                             int tid, float* red) {
    int w = tid >> 5, lane = tid & 31;
    if (w == 0) {
        float s = 0.f;
#pragma unroll
        for (int i = 0; i < 8; ++i) s += y[lane + 32 * i];
        s = warp_reduce(s);
        if (lane == 0) red[0] = s * (1.f / 256.f);
    }
    __syncthreads();
    float mu = red[0];
    if (w == 0) {
        float s = 0.f;
#pragma unroll
        for (int i = 0; i < 8; ++i) {
            float d = y[lane + 32 * i] - mu;
            s += d * d;
        }
        s = warp_reduce(s);
        if (lane == 0) red[1] = 1.f / sqrtf(s * (1.f / 256.f) + 1e-5f);
    }
    __syncthreads();
    float inv = red[1];
    if (tid < 256) out[tid] = (y[tid] - mu) * inv * gma[tid] + bta[tid];
    __syncthreads();
}

// ---------------------------------------------------------------------------
// Setup kernels
// ---------------------------------------------------------------------------
__global__ void fold1(const float* __restrict__ Wo, const float* __restrict__ Wv) {
    int i = blockIdx.x, j = threadIdx.x;
    float s = 0.f;
    for (int k = 0; k < SG; ++k) s += Wo[i * SG + k] * Wv[k * SG + j];
    g_A[i * SG + j] = s;
}

__global__ void fold2(const float* __restrict__ Wg, const float* __restrict__ bg,
                      const float* __restrict__ Wo, const float* __restrict__ bv,
                      const float* __restrict__ bo) {
    int i = blockIdx.x, j = threadIdx.x;
    float s = Wg[i * SG + j];
    for (int k = 0; k < SG; ++k) s += g_A[i * SG + k] * Wg[k * SG + j];
    g_Bm[i * SG + j] = s;
    if (j == 0) {
        float t = bg[i] + bo[i];
        for (int k = 0; k < SG; ++k) t += g_A[i * SG + k] * bg[k];
        for (int k = 0; k < SG; ++k) t += Wo[i * SG + k] * bv[k];
        g_d[i] = t;
    }
}

__global__ void fold3(const float* __restrict__ W2, const float* __restrict__ b2) {
    int i = blockIdx.x, j = threadIdx.x;
    float s = 0.f;
    for (int k = 0; k < SG; ++k) s += g_Bm[i * SG + k] * W2[k * H1DIM + j];
    g_C[i * H1DIM + j] = s;
    if (j == 0) {
        float t = g_d[i];
        for (int k = 0; k < SG; ++k) t += g_Bm[i * SG + k] * b2[k];
        g_e[i] = t;
    }
}

__global__ void fold4(const float* __restrict__ Wf1, const float* __restrict__ bf1,
                      const float* __restrict__ ln1g, const float* __restrict__ ln1b) {
    int r = blockIdx.x, j = threadIdx.x;
    __shared__ float s1[SG], s2[SG];
    float wv = Wf1[(size_t)r * SG + j];
    float wg = wv * ln1g[j];
    g_wf1g[(size_t)r * SG + j] = wg;
    s1[j] = wg;
    s2[j] = wv * ln1b[j];
    __syncthreads();
    for (int o = 128; o; o >>= 1) {
        if (j < o) { s1[j] += s1[j + o]; s2[j] += s2[j + o]; }
        __syncthreads();
    }
    if (j == 0) { g_Rff[r] = s1[0]; g_c1[r] = s2[0] + bf1[r]; }
}

__global__ void fold5(const float* __restrict__ W1, const float* __restrict__ b1,
                      const float* __restrict__ ln2g, const float* __restrict__ ln2b) {
    int r = blockIdx.x, j = threadIdx.x;
    __shared__ float s1[SG], s2[SG];
    float wv = W1[(size_t)r * H1DIM + 256 + j];
    float wg = wv * ln2g[j];
    g_w1gg[(size_t)r * SG + j] = wg;
    s1[j] = wg;
    s2[j] = wv * ln2b[j];
    __syncthreads();
    for (int o = 128; o; o >>= 1) {
        if (j < o) { s1[j] += s1[j + o]; s2[j] += s2[j + o]; }
        __syncthreads();
    }
    if (j == 0) { g_R1[r] = s1[0]; g_k1[r] = s2[0] + b1[r]; }
}

// ---------------------------------------------------------------------------
// Main chain: 16-CTA cluster, 512 thr/CTA, 2 mbarrier syncs/step.
// R9 structure (coalesced partial writes, strided reads) + vectorized LDS
// in the p1/p2 operand reads (the ONLY change vs R9).
// ---------------------------------------------------------------------------
#define SEQ6_SMEM_FLOATS (32 * SG + 32 * SG + 128 * SG + SG + SG + SG + 32 + 128 + 512 + 128 + 128 + 32)
#define SEQ6_SMEM_BYTES (SEQ6_SMEM_FLOATS * 4)

__global__ void __launch_bounds__(512, 1) seq6_kernel(
    const float* __restrict__ gnn,
    const float* __restrict__ W1, const float* __restrict__ b1,
    const float* __restrict__ W2, const float* __restrict__ b2,
    const float* __restrict__ Wf2, const float* __restrict__ bf2,
    const float* __restrict__ ln1g, const float* __restrict__ ln1b) {
    extern __shared__ __align__(16) float sm[];
    float* w1ms  = sm;                  // [32][256]  W1 m-columns slice
    float* w1gs  = w1ms + 32 * SG;      // [32][256]  W1gg slice
    float* wf1s  = w1gs + 32 * SG;      // [128][256] Wf1g slice
    float* mbuf  = wf1s + 128 * SG;     // 256
    float* y1s   = mbuf + SG;           // 256
    float* y2s   = y1s + SG;            // 256 (raw y2)
    float* h1loc = y2s + SG;            // 32
    float* ffloc = h1loc + 32;          // 128
    float* p2tmp = ffloc + 128;         // 512
    float* rffs  = p2tmp + 512;         // 128
    float* c1s   = rffs + 128;          // 128
    float* redsm = c1s + 128;           // 32
    __shared__ __align__(8) unsigned long long mb[2];

    int tid = threadIdx.x, w = tid >> 5, lane = tid & 31;
    unsigned rank;
    asm("mov.u32 %0, %%cluster_ctarank;" : "=r"(rank));
    unsigned a_mb = smem_u32(mb);

    // resident smem weights
    for (int i = tid; i < 32 * SG; i += 512) {
        int r = i >> 8, j = i & 255;
        w1ms[i] = W1[(size_t)(rank * 32 + r) * H1DIM + j];
        w1gs[i] = g_w1gg[(size_t)(rank * 32 + r) * SG + j];
    }
    for (int i = tid; i < 128 * SG; i += 512)
        wf1s[i] = g_wf1g[(size_t)rank * 128 * SG + i];
    if (tid < 128) {
        rffs[tid] = g_Rff[rank * 128 + tid];
        c1s[tid]  = g_c1[rank * 128 + tid];
    }

    // persistent register weights
    float pw[32];
    {
        const float* psrc = (tid < 256)
            ? (W2 + (size_t)tid * H1DIM + rank * 32)
            : (g_C + (size_t)(tid - 256) * H1DIM + rank * 32);
#pragma unroll
        for (int c = 0; c < 32; ++c) pw[c] = psrc[c];
    }
    float wf2c[64];
    {
        int r2 = tid & 255, half = tid >> 8;
        const float* wsrc = Wf2 + (size_t)r2 * DFF + rank * 128 + half * 64;
#pragma unroll
        for (int c = 0; c < 64; ++c) wf2c[c] = wsrc[c];
    }
    const int g1a = rank * 32 + w, g1b = g1a + 16;
    float b1a = b1[g1a], b1b = b1[g1b];
    float R1a = g_R1[g1a], R1b = g_R1[g1b];
    float k1a = g_k1[g1a], k1b = g_k1[g1b];
    float e_r = (tid < 256) ? g_e[tid] : 0.f;
    float bf2_r = (tid < 256) ? bf2[tid] : 0.f;
    float l1g = 0.f, l1b_ = 0.f;
    if (tid < 256) { l1g = ln1g[tid]; l1b_ = ln1b[tid]; }
    float b2row = 0.f;
    int hrow = -1;
    if (tid >= 256 && tid < 256 + 16) {
        hrow = rank * 16 + (tid - 256);
        b2row = b2[hrow];
    }

    if (tid < 2)
        asm volatile("mbarrier.init.shared.b64 [%0], %1;"
                     :: "r"(a_mb + tid * 8), "r"(16) : "memory");
    if (tid < 256) {
        y2s[tid] = 0.f;
        mbuf[tid] = gnn[(size_t)tid];  // m_0
    }
    __syncthreads();
    CLU_SYNC();

    float md0 = row_dot<SG>(w1ms + w * SG, mbuf, lane);
    float md1 = row_dot<SG>(w1ms + (w + 16) * SG, mbuf, lane);
    float mu1 = 0.f, inv1 = 0.f;

    for (int t = 0; t < NSTEPS; ++t) {
        unsigned par = (unsigned)(t & 1);

        float mnext = 0.f;
        if (tid < 256)
            mnext = gnn[(size_t)((t + 1) & (NNODES - 1)) * SG + tid];

        // S1 g-dot over RAW y2; concurrent y2-stats finalize
        float dg0 = row_dot<SG>(w1gs + w * SG, y2s, lane);
        float dg1 = row_dot<SG>(w1gs + (w + 16) * SG, y2s, lane);
        if (t > 0 && tid == 0) {
            float s = 0.f, s2 = 0.f;
#pragma unroll
            for (int i = 0; i < 8; ++i) { s += redsm[2 * i]; s2 += redsm[2 * i + 1]; }
            float mu = s * (1.f / 256.f);
            float var = s2 * (1.f / 256.f) - mu * mu;
            redsm[16] = mu;
            redsm[17] = 1.f / sqrtf(var + 1e-5f);
        }
        __syncthreads();

        // S1 epilogue -> h1 slice
        {
            float v0, v1;
            if (t == 0) {
                v0 = md0 + b1a;
                v1 = md1 + b1b;
            } else {
                float mu2 = redsm[16], inv2 = redsm[17];
                v0 = md0 + inv2 * (dg0 - mu2 * R1a) + k1a;
                v1 = md1 + inv2 * (dg1 - mu2 * R1b) + k1b;
            }
            if (lane == 0) {
                h1loc[w] = fmaxf(v0, 0.f);
                h1loc[w + 16] = fmaxf(v1, 0.f);
            }
        }
        __syncthreads();

        // p1 partials: float4 h1loc loads, sequential accumulation (c order)
        {
            const float4* h4 = reinterpret_cast<const float4*>(h1loc);
            float acc = 0.f;
#pragma unroll
            for (int c4 = 0; c4 < 8; ++c4) {
                float4 hv = h4[c4];
                acc += pw[4 * c4 + 0] * hv.x;
                acc += pw[4 * c4 + 1] * hv.y;
                acc += pw[4 * c4 + 2] * hv.z;
                acc += pw[4 * c4 + 3] * hv.w;
            }
            if (tid < 256) g_ph[rank * SG + tid] = acc;
            else           g_p1[rank * SG + (tid - 256)] = acc;
        }
        if (tid < 256) mbuf[tid] = mnext;
        __syncthreads();
        if (tid < 16) arrive_remote_rel(a_mb + 0 * 8, (unsigned)tid);

        // shadow: m-dot for t+1
        md0 = row_dot<SG>(w1ms + w * SG, mbuf, lane);
        md1 = row_dot<SG>(w1ms + (w + 16) * SG, mbuf, lane);

        bar_wait_acq(a_mb + 0 * 8, par);                   // sync 1

        // reduce y1 (+ warp stats); h rows
        float y1v = 0.f;
        if (tid < 256) {
            float s = e_r;
#pragma unroll
            for (int k = 0; k < 16; ++k) s += g_p1[k * SG + tid];
            y1v = s;
            y1s[tid] = s;
            float sa = s, s2a = s * s;
#pragma unroll
            for (int o = 16; o; o >>= 1) {
                sa += __shfl_xor_sync(0xffffffffu, sa, o);
                s2a += __shfl_xor_sync(0xffffffffu, s2a, o);
            }
            if (lane == 0) { redsm[2 * w] = sa; redsm[2 * w + 1] = s2a; }
        } else if (hrow >= 0) {
            float s = b2row;
#pragma unroll
            for (int k = 0; k < 16; ++k) s += g_ph[k * SG + hrow];
            g_h_all[(size_t)t * SG + hrow] = s;
        }
        __syncthreads();

        // z = Wf1g @ y1 (raw), concurrent LN1 stats finalize
        float z[8];
#pragma unroll
        for (int i = 0; i < 8; ++i)
            z[i] = row_dot<SG>(wf1s + (w + 16 * i) * SG, y1s, lane);
        if (tid == 0) {
            float s = 0.f, s2 = 0.f;
#pragma unroll
            for (int i = 0; i < 8; ++i) { s += redsm[2 * i]; s2 += redsm[2 * i + 1]; }
            float mu = s * (1.f / 256.f);
            float var = s2 * (1.f / 256.f) - mu * mu;
            redsm[16] = mu;
            redsm[17] = 1.f / sqrtf(var + 1e-5f);
        }
        __syncthreads();

        mu1 = redsm[16];
        inv1 = redsm[17];
        // ff epilogue (LN1 fold)
        if (lane == 0) {
#pragma unroll
            for (int i = 0; i < 8; ++i) {
                int r = w + 16 * i;
                ffloc[r] = fmaxf(inv1 * (z[i] - mu1 * rffs[r]) + c1s[r], 0.f);
            }
        }
        __syncthreads();

        // p2 partials: float4 ffloc loads, sequential accumulation
        {
            int half = tid >> 8;
            const float4* fl4 = reinterpret_cast<const float4*>(ffloc + half * 64);
            float a2 = 0.f;
#pragma unroll
            for (int c4 = 0; c4 < 16; ++c4) {
                float4 fv = fl4[c4];
                a2 += wf2c[4 * c4 + 0] * fv.x;
                a2 += wf2c[4 * c4 + 1] * fv.y;
                a2 += wf2c[4 * c4 + 2] * fv.z;
                a2 += wf2c[4 * c4 + 3] * fv.w;
            }
            p2tmp[tid] = a2;
        }
        __syncthreads();
        if (tid < 256) g_p2[rank * SG + tid] = p2tmp[tid] + p2tmp[tid + 256];
        __syncthreads();
        if (tid < 16) arrive_remote_rel(a_mb + 1 * 8, (unsigned)tid);
        bar_wait_acq(a_mb + 1 * 8, par);                   // sync 2

        // reduce y2 raw + stats
        if (tid < 256) {
            float x = (y1v - mu1) * inv1 * l1g + l1b_;
            float s = x + bf2_r;
#pragma unroll
            for (int k = 0; k < 16; ++k) s += g_p2[k * SG + tid];
            y2s[tid] = s;
            float sa = s, s2a = s * s;
#pragma unroll
            for (int o = 16; o; o >>= 1) {
                sa += __shfl_xor_sync(0xffffffffu, sa, o);
                s2a += __shfl_xor_sync(0xffffffffu, s2a, o);
            }
            if (lane == 0) { redsm[2 * w] = sa; redsm[2 * w + 1] = s2a; }
        }
        __syncthreads();
    }
    CLU_SYNC();
}

// ---------------------------------------------------------------------------
// Fallback (cluster size < 16): R4-proven streaming kernel, CL=8.
// ---------------------------------------------------------------------------
__global__ void __launch_bounds__(1024, 1) seq_fallback8(
    const float* __restrict__ gnn,
    const float* __restrict__ W1, const float* __restrict__ b1,
    const float* __restrict__ W2, const float* __restrict__ b2,
    const float* __restrict__ Wg, const float* __restrict__ bg,
    const float* __restrict__ Wv, const float* __restrict__ bv,
    const float* __restrict__ Wo, const float* __restrict__ bo,
    const float* __restrict__ Wf1, const float* __restrict__ bf1,
    const float* __restrict__ Wf2, const float* __restrict__ bf2,
    const float* __restrict__ ln1g, const float* __restrict__ ln1b,
    const float* __restrict__ ln2g, const float* __restrict__ ln2b) {
    constexpr int CL = 8;
    constexpr int R_H1 = H1DIM / CL, R_SG = SG / CL, R_FF = DFF / CL;
    __shared__ __align__(16) float cat[H1DIM];
    __shared__ __align__(16) float h1s[H1DIM];
    __shared__ __align__(16) float hs[SG];
    __shared__ __align__(16) float gns[SG];
    __shared__ __align__(16) float vvs[SG];
    __shared__ __align__(16) float ys[SG];
    __shared__ __align__(16) float xs[SG];
    __shared__ __align__(16) float ff1s[DFF];
    __shared__ float red[2];

    int tid = threadIdx.x, w = tid >> 5, lane = tid & 31;
    unsigned rank;
    asm("mov.u32 %0, %%cluster_ctarank;" : "=r"(rank));
    if (tid < 256) cat[256 + tid] = 0.f;
    __syncthreads();

    for (int t = 0; t < NSTEPS; ++t) {
        if (tid < 256) cat[tid] = gnn[(size_t)(t & (NNODES - 1)) * SG + tid];
        __syncthreads();
        for (int r = w; r < R_H1; r += 32) {
            int gr = rank * R_H1 + r;
            float s = row_dot<H1DIM>(W1 + (size_t)gr * H1DIM, cat, lane);
            if (lane == 0) g_bh1[gr] = fmaxf(s + b1[gr], 0.f);
        }
        CLU_SYNC();
        for (int i = tid; i < H1DIM; i += 1024) h1s[i] = g_bh1[i];
        __syncthreads();
        float* gh = g_h_all + (size_t)t * SG;
        for (int r = w; r < R_SG; r += 32) {
            int gr = rank * R_SG + r;
            float s = row_dot<H1DIM>(W2 + (size_t)gr * H1DIM, h1s, lane);
            if (lane == 0) gh[gr] = s + b2[gr];
        }
        CLU_SYNC();
        for (int i = tid; i < SG; i += 1024) hs[i] = gh[i];
        __syncthreads();
        for (int r = w; r < R_SG; r += 32) {
            int gr = rank * R_SG + r;
            float s = row_dot<SG>(Wg + (size_t)gr * SG, hs, lane);
            if (lane == 0) g_by1[gr] = s + bg[gr];
        }
        CLU_SYNC();
        for (int i = tid; i < SG; i += 1024) gns[i] = g_by1[i];
        __syncthreads();
        for (int r = w; r < R_SG; r += 32) {
            int gr = rank * R_SG + r;
            float s = row_dot<SG>(Wv + (size_t)gr * SG, gns, lane);
            if (lane == 0) g_by2[gr] = s + bv[gr];
        }
        CLU_SYNC();
        for (int i = tid; i < SG; i += 1024) vvs[i] = g_by2[i];
        __syncthreads();
        for (int r = w; r < R_SG; r += 32) {
            int gr = rank * R_SG + r;
            float s = row_dot<SG>(Wo + (size_t)gr * SG, vvs, lane);
            if (lane == 0) g_by1[gr] = gns[gr] + (s + bo[gr]);
        }
        CLU_SYNC();
        for (int i = tid; i < SG; i += 1024) ys[i] = g_by1[i];
        __syncthreads();
        layernorm256(ys, xs, ln1g, ln1b, tid, red);
        for (int r = w; r < R_FF; r += 32) {
            int gr = rank * R_FF + r;
            float s = row_dot<SG>(Wf1 + (size_t)gr * SG, xs, lane);
            if (lane == 0) g_bff[gr] = fmaxf(s + bf1[gr], 0.f);
        }
        CLU_SYNC();
        for (int i = tid; i < DFF; i += 1024) ff1s[i] = g_bff[i];
        __syncthreads();
        for (int r = w; r < R_SG; r += 32) {
            int gr = rank * R_SG + r;
            float s = row_dot<DFF>(Wf2 + (size_t)gr * DFF, ff1s, lane);
            if (lane == 0) g_by2[gr] = xs[gr] + (s + bf2[gr]);
        }
        CLU_SYNC();
        for (int i = tid; i < SG; i += 1024) ys[i] = g_by2[i];
        __syncthreads();
        layernorm256(ys, cat + 256, ln2g, ln2b, tid, red);
    }
}

// ---------------------------------------------------------------------------
// Sampler: T=8 timesteps per block (R9 configuration).
// ---------------------------------------------------------------------------
#define SAMP_T 8
#define SAMP_THREADS 512
#define SAMP_SMEM ((SAMP_T * SG + SAMP_T * NROW) * 4)

__global__ void __launch_bounds__(SAMP_THREADS) sample_kernel8(
    const float* __restrict__ u,
    const float* __restrict__ Wr, const float* __restrict__ br,
    float* __restrict__ out) {
    extern __shared__ __align__(16) float sm[];
    float* hsm = sm;
    float* probs = sm + SAMP_T * SG;
    __shared__ int cnt[SAMP_T][4];
    __shared__ int sel[SAMP_T];

    int tb = blockIdx.x * SAMP_T;
    int tid = threadIdx.x, w = tid >> 5, lane = tid & 31;

    for (int i = tid; i < SAMP_T * SG; i += SAMP_THREADS)
        hsm[i] = g_h_all[(size_t)tb * SG + i];
    if (tid < SAMP_T * 4) cnt[tid >> 2][tid & 3] = 0;
    __syncthreads();

    for (int r = w; r < NROW; r += 16) {
        const float* Wrow = Wr + (size_t)r * SG;
        float brv = br[r];
#pragma unroll
        for (int j = 0; j < SAMP_T; ++j) {
            float s = row_dot<SG>(Wrow, hsm + j * SG, lane);
            if (lane == 0) {
                float z = s + brv;
                float p;
                if (z >= 0.f) {
                    p = 1.f / (1.f + expf(-z));
                } else {
                    float e = expf(z);
                    p = e / (1.f + e);
                }
                probs[j * NROW + r] = p;
            }
        }
    }
    __syncthreads();

#pragma unroll
    for (int j = 0; j < SAMP_T; ++j) {
        const float* __restrict__ ut = u + (size_t)(tb + j) * 4 * NROW;
        int c[4] = {0, 0, 0, 0};
#pragma unroll
        for (int k = 0; k < 4; ++k)
#pragma unroll
            for (int i = 0; i < NROW / SAMP_THREADS; ++i) {
                int n = tid + SAMP_THREADS * i;
                c[k] += (ut[k * NROW + n] < probs[j * NROW + n]) ? 1 : 0;
            }
#pragma unroll
        for (int k = 0; k < 4; ++k) {
            int s = c[k];
#pragma unroll
            for (int o = 16; o; o >>= 1) s += __shfl_xor_sync(0xffffffffu, s, o);
            if (lane == 0) atomicAdd(&cnt[j][k], s);
        }
    }
    __syncthreads();

    if (tid < SAMP_T) {
        int idx = 0;
        for (int k = 3; k >= 0; --k) {
            int ck = cnt[tid][k];
            bool valid = (ck == 0) || (ck >= 2 && ck <= 6);
            if (valid) idx = k;
        }
        sel[tid] = idx;
    }
    __syncthreads();

#pragma unroll
    for (int j = 0; j < SAMP_T; ++j) {
        const float* __restrict__ ut = u + (size_t)(tb + j) * 4 * NROW;
        int idx = sel[j];
#pragma unroll
        for (int i = 0; i < NROW / SAMP_THREADS; ++i) {
            int n = tid + SAMP_THREADS * i;
            out[(size_t)(tb + j) * NROW + n] =
                (ut[idx * NROW + n] < probs[j * NROW + n]) ? 1.f : 0.f;
        }
    }
}

extern "C" void kernel_launch(void* const* d_in, const int* in_sizes, int n_in,
                              void* d_out, int out_size) {
    (void)in_sizes; (void)n_in; (void)out_size;
    const float* gnn  = (const float*)d_in[0];
    const float* u    = (const float*)d_in[2];
    const float* W1   = (const float*)d_in[3];
    const float* b1   = (const float*)d_in[4];
    const float* W2   = (const float*)d_in[5];
    const float* b2   = (const float*)d_in[6];
    const float* Wr   = (const float*)d_in[7];
    const float* br   = (const float*)d_in[8];
    const float* Wg   = (const float*)d_in[9];
    const float* bg   = (const float*)d_in[10];
    const float* Wv   = (const float*)d_in[11];
    const float* bv   = (const float*)d_in[12];
    const float* Wo   = (const float*)d_in[13];
    const float* bo   = (const float*)d_in[14];
    const float* Wf1  = (const float*)d_in[15];
    const float* bf1  = (const float*)d_in[16];
    const float* Wf2  = (const float*)d_in[17];
    const float* bf2  = (const float*)d_in[18];
    const float* ln1g = (const float*)d_in[19];
    const float* ln1b = (const float*)d_in[20];
    const float* ln2g = (const float*)d_in[21];
    const float* ln2b = (const float*)d_in[22];

    // folds (deterministic, every call)
    fold1<<<SG, SG>>>(Wo, Wv);
    fold2<<<SG, SG>>>(Wg, bg, Wo, bv, bo);
    fold3<<<SG, H1DIM>>>(W2, b2);
    fold4<<<DFF, SG>>>(Wf1, bf1, ln1g, ln1b);
    fold5<<<H1DIM, SG>>>(W1, b1, ln2g, ln2b);

    cudaFuncSetAttribute(seq6_kernel,
                         cudaFuncAttributeMaxDynamicSharedMemorySize, SEQ6_SMEM_BYTES);
    cudaFuncSetAttribute(seq6_kernel,
                         cudaFuncAttributeNonPortableClusterSizeAllowed, 1);

    cudaError_t e = cudaErrorUnknown;
    {
        cudaLaunchConfig_t cfg = {};
        cfg.gridDim = dim3(16, 1, 1);
        cfg.blockDim = dim3(512, 1, 1);
        cfg.dynamicSmemBytes = SEQ6_SMEM_BYTES;
        cfg.stream = 0;
        cudaLaunchAttribute at[1];
        at[0].id = cudaLaunchAttributeClusterDimension;
        at[0].val.clusterDim.x = 16;
        at[0].val.clusterDim.y = 1;
        at[0].val.clusterDim.z = 1;
        cfg.attrs = at;
        cfg.numAttrs = 1;
        e = cudaLaunchKernelEx(&cfg, seq6_kernel,
                               gnn, W1, b1, W2, b2, Wf2, bf2, ln1g, ln1b);
    }
    if (e != cudaSuccess) {
        cudaLaunchConfig_t cfg = {};
        cfg.gridDim = dim3(8, 1, 1);
        cfg.blockDim = dim3(1024, 1, 1);
        cfg.dynamicSmemBytes = 0;
        cfg.stream = 0;
        cudaLaunchAttribute at[1];
        at[0].id = cudaLaunchAttributeClusterDimension;
        at[0].val.clusterDim.x = 8;
        at[0].val.clusterDim.y = 1;
        at[0].val.clusterDim.z = 1;
        cfg.attrs = at;
        cfg.numAttrs = 1;
        cudaLaunchKernelEx(&cfg, seq_fallback8,
                           gnn, W1, b1, W2, b2, Wg, bg, Wv, bv, Wo, bo,
                           Wf1, bf1, Wf2, bf2, ln1g, ln1b, ln2g, ln2b);
    }

    cudaFuncSetAttribute(sample_kernel8,
                         cudaFuncAttributeMaxDynamicSharedMemorySize, SAMP_SMEM);
    sample_kernel8<<<NSTEPS / SAMP_T, SAMP_THREADS, SAMP_SMEM>>>(
        u, Wr, br, (float*)d_out);
}

// round 12
// speedup vs baseline: 1.1899x; 1.0312x over previous
#include <cuda_runtime.h>
#include <math.h>

#define NSTEPS 8192
#define NNODES 4096
#define SG 256
#define NROW 2048
#define DFF 2048
#define H1DIM 512

// h_t for every step (consumed by the sampler kernel)
__device__ float g_h_all[NSTEPS * SG];
// folded matrices (recomputed deterministically every launch)
__device__ float g_A[SG * SG];       // Wo @ Wv
__device__ float g_Bm[SG * SG];      // (I + A) @ Wg
__device__ float g_d[SG];            // (I+A)@bg + Wo@bv + bo
__device__ float g_C[SG * H1DIM];    // Bm @ W2
__device__ float g_e[SG];            // Bm @ b2 + d
// LN1 fold: Wf1g = Wf1*diag(ln1g), Rff = rowsum, c1 = Wf1@ln1b + bf1
__device__ float g_wf1g[DFF * SG];
__device__ float g_Rff[DFF];
__device__ float g_c1[DFF];
// LN2 fold into W1 g-columns
__device__ float g_w1gg[H1DIM * SG];
__device__ float g_R1[H1DIM];
__device__ float g_k1[H1DIM];
// cross-CTA partial buffers (L2-resident), coalesced writes [rank][entry].
// g_ph is parity double-buffered: its reduce happens in the sync2 wait
// shadow, which may overlap other CTAs' next-step writes.
__device__ float g_p1[16 * SG];      // y1 partials
__device__ float g_ph2[2][16 * SG];  // h partials (double-buffered)
__device__ float g_p2[16 * SG];      // y2 partials
// fallback broadcast buffers
__device__ float g_bh1[H1DIM];
__device__ float g_by1[SG];
__device__ float g_bff[DFF];
__device__ float g_by2[SG];

#define CLU_SYNC()                                                        \
    do {                                                                  \
        asm volatile("barrier.cluster.arrive.aligned;" ::: "memory");    \
        asm volatile("barrier.cluster.wait.aligned;" ::: "memory");      \
    } while (0)

__device__ __forceinline__ unsigned smem_u32(const void* p) {
    return (unsigned)__cvta_generic_to_shared(p);
}

__device__ __forceinline__ void arrive_remote_rel(unsigned lmbar, unsigned rank) {
    unsigned r;
    asm volatile("mapa.shared::cluster.u32 %0, %1, %2;" : "=r"(r) : "r"(lmbar), "r"(rank));
    asm volatile("mbarrier.arrive.release.cluster.shared::cluster.b64 _, [%0];"
                 :: "r"(r) : "memory");
}

__device__ __forceinline__ void bar_wait_acq(unsigned mbar, unsigned parity) {
    asm volatile(
        "{\n\t.reg .pred P;\n\t"
        "WL%=:\n\t"
        "mbarrier.try_wait.parity.acquire.cluster.shared::cta.b64 P, [%0], %1, 0x989680;\n\t"
        "@P bra WD%=;\n\t"
        "bra WL%=;\n\t"
        "WD%=:\n\t}"
        :: "r"(mbar), "r"(parity) : "memory");
}

__device__ __forceinline__ float warp_reduce(float v) {
#pragma unroll
    for (int o = 16; o; o >>= 1) v += __shfl_xor_sync(0xffffffffu, v, o);
    return v;
}

template <int C>
__device__ __forceinline__ float row_dot(const float* __restrict__ W,
                                         const float* __restrict__ x, int lane) {
    const float4* __restrict__ W4 = reinterpret_cast<const float4*>(W);
    const float4* __restrict__ x4 = reinterpret_cast<const float4*>(x);
    float s = 0.f;
#pragma unroll
    for (int c = 0; c < C / 4; c += 32) {
        float4 w = W4[c + lane];
        float4 xv = x4[c + lane];
        s += w.x * xv.x + w.y * xv.y + w.z * xv.z + w.w * xv.w;
    }
    return warp_reduce(s);
}

// per-thread stats finalize from warp partials (same expression/order as the
// old tid0 version -> bit-identical, just replicated across threads)
__device__ __forceinline__ void stats_from_redsm(const float* __restrict__ redsm,
                                                 float& mu, float& inv) {
    float s = 0.f, s2 = 0.f;
#pragma unroll
    for (int i = 0; i < 8; ++i) { s += redsm[2 * i]; s2 += redsm[2 * i + 1]; }
    mu = s * (1.f / 256.f);
    float var = s2 * (1.f / 256.f) - mu * mu;
    inv = 1.f / sqrtf(var + 1e-5f);
}

// two-pass LN (fallback kernel only)
__device__ __forceinline__ void layernorm256(const float* __restrict__ y,
                                             float* __restrict__ out,
                                             const float* __restrict__ gma,
                                             const float* __restrict__ bta,
                                             int tid, float* red) {
    int w = tid >> 5, lane = tid & 31;
    if (w == 0) {
        float s = 0.f;
#pragma unroll
        for (int i = 0; i < 8; ++i) s += y[lane + 32 * i];
        s = warp_reduce(s);
        if (lane == 0) red[0] = s * (1.f / 256.f);
    }
    __syncthreads();
    float mu = red[0];
    if (w == 0) {
        float s = 0.f;
#pragma unroll
        for (int i = 0; i < 8; ++i) {
            float d = y[lane + 32 * i] - mu;
            s += d * d;
        }
        s = warp_reduce(s);
        if (lane == 0) red[1] = 1.f / sqrtf(s * (1.f / 256.f) + 1e-5f);
    }
    __syncthreads();
    float inv = red[1];
    if (tid < 256) out[tid] = (y[tid] - mu) * inv * gma[tid] + bta[tid];
    __syncthreads();
}

// ---------------------------------------------------------------------------
// Setup kernels
// ---------------------------------------------------------------------------
__global__ void fold1(const float* __restrict__ Wo, const float* __restrict__ Wv) {
    int i = blockIdx.x, j = threadIdx.x;
    float s = 0.f;
    for (int k = 0; k < SG; ++k) s += Wo[i * SG + k] * Wv[k * SG + j];
    g_A[i * SG + j] = s;
}

__global__ void fold2(const float* __restrict__ Wg, const float* __restrict__ bg,
                      const float* __restrict__ Wo, const float* __restrict__ bv,
                      const float* __restrict__ bo) {
    int i = blockIdx.x, j = threadIdx.x;
    float s = Wg[i * SG + j];
    for (int k = 0; k < SG; ++k) s += g_A[i * SG + k] * Wg[k * SG + j];
    g_Bm[i * SG + j] = s;
    if (j == 0) {
        float t = bg[i] + bo[i];
        for (int k = 0; k < SG; ++k) t += g_A[i * SG + k] * bg[k];
        for (int k = 0; k < SG; ++k) t += Wo[i * SG + k] * bv[k];
        g_d[i] = t;
    }
}

__global__ void fold3(const float* __restrict__ W2, const float* __restrict__ b2) {
    int i = blockIdx.x, j = threadIdx.x;
    float s = 0.f;
    for (int k = 0; k < SG; ++k) s += g_Bm[i * SG + k] * W2[k * H1DIM + j];
    g_C[i * H1DIM + j] = s;
    if (j == 0) {
        float t = g_d[i];
        for (int k = 0; k < SG; ++k) t += g_Bm[i * SG + k] * b2[k];
        g_e[i] = t;
    }
}

__global__ void fold4(const float* __restrict__ Wf1, const float* __restrict__ bf1,
                      const float* __restrict__ ln1g, const float* __restrict__ ln1b) {
    int r = blockIdx.x, j = threadIdx.x;
    __shared__ float s1[SG], s2[SG];
    float wv = Wf1[(size_t)r * SG + j];
    float wg = wv * ln1g[j];
    g_wf1g[(size_t)r * SG + j] = wg;
    s1[j] = wg;
    s2[j] = wv * ln1b[j];
    __syncthreads();
    for (int o = 128; o; o >>= 1) {
        if (j < o) { s1[j] += s1[j + o]; s2[j] += s2[j + o]; }
        __syncthreads();
    }
    if (j == 0) { g_Rff[r] = s1[0]; g_c1[r] = s2[0] + bf1[r]; }
}

__global__ void fold5(const float* __restrict__ W1, const float* __restrict__ b1,
                      const float* __restrict__ ln2g, const float* __restrict__ ln2b) {
    int r = blockIdx.x, j = threadIdx.x;
    __shared__ float s1[SG], s2[SG];
    float wv = W1[(size_t)r * H1DIM + 256 + j];
    float wg = wv * ln2g[j];
    g_w1gg[(size_t)r * SG + j] = wg;
    s1[j] = wg;
    s2[j] = wv * ln2b[j];
    __syncthreads();
    for (int o = 128; o; o >>= 1) {
        if (j < o) { s1[j] += s1[j + o]; s2[j] += s2[j + o]; }
        __syncthreads();
    }
    if (j == 0) { g_R1[r] = s1[0]; g_k1[r] = s2[0] + b1[r]; }
}

// ---------------------------------------------------------------------------
// Main chain: 16-CTA cluster, 512 thr/CTA, 2 mbarrier syncs/step,
// 7 __syncthreads/step, per-thread stats finalize, h-reduce in sync2 shadow.
// ---------------------------------------------------------------------------
#define SEQ7_SMEM_FLOATS (32 * SG + 32 * SG + 128 * SG + SG + SG + SG + 32 + 128 + 512 + 128 + 128 + 32)
#define SEQ7_SMEM_BYTES (SEQ7_SMEM_FLOATS * 4)

__global__ void __launch_bounds__(512, 1) seq7_kernel(
    const float* __restrict__ gnn,
    const float* __restrict__ W1, const float* __restrict__ b1,
    const float* __restrict__ W2, const float* __restrict__ b2,
    const float* __restrict__ Wf2, const float* __restrict__ bf2,
    const float* __restrict__ ln1g, const float* __restrict__ ln1b) {
    extern __shared__ __align__(16) float sm[];
    float* w1ms  = sm;                  // [32][256]  W1 m-columns slice
    float* w1gs  = w1ms + 32 * SG;      // [32][256]  W1gg slice
    float* wf1s  = w1gs + 32 * SG;      // [128][256] Wf1g slice
    float* mbuf  = wf1s + 128 * SG;     // 256
    float* y1s   = mbuf + SG;           // 256
    float* y2s   = y1s + SG;            // 256 (raw y2)
    float* h1loc = y2s + SG;            // 32
    float* ffloc = h1loc + 32;          // 128
    float* p2tmp = ffloc + 128;         // 512
    float* rffs  = p2tmp + 512;         // 128
    float* c1s   = rffs + 128;          // 128
    float* redsm = c1s + 128;           // 16 used
    __shared__ __align__(8) unsigned long long mb[2];

    int tid = threadIdx.x, w = tid >> 5, lane = tid & 31;
    unsigned rank;
    asm("mov.u32 %0, %%cluster_ctarank;" : "=r"(rank));
    unsigned a_mb = smem_u32(mb);

    // resident smem weights
    for (int i = tid; i < 32 * SG; i += 512) {
        int r = i >> 8, j = i & 255;
        w1ms[i] = W1[(size_t)(rank * 32 + r) * H1DIM + j];
        w1gs[i] = g_w1gg[(size_t)(rank * 32 + r) * SG + j];
    }
    for (int i = tid; i < 128 * SG; i += 512)
        wf1s[i] = g_wf1g[(size_t)rank * 128 * SG + i];
    if (tid < 128) {
        rffs[tid] = g_Rff[rank * 128 + tid];
        c1s[tid]  = g_c1[rank * 128 + tid];
    }

    // persistent register weights
    float pw[32];
    {
        const float* psrc = (tid < 256)
            ? (W2 + (size_t)tid * H1DIM + rank * 32)
            : (g_C + (size_t)(tid - 256) * H1DIM + rank * 32);
#pragma unroll
        for (int c = 0; c < 32; ++c) pw[c] = psrc[c];
    }
    float wf2c[64];
    {
        int r2 = tid & 255, half = tid >> 8;
        const float* wsrc = Wf2 + (size_t)r2 * DFF + rank * 128 + half * 64;
#pragma unroll
        for (int c = 0; c < 64; ++c) wf2c[c] = wsrc[c];
    }
    const int g1a = rank * 32 + w, g1b = g1a + 16;
    float b1a = b1[g1a], b1b = b1[g1b];
    float R1a = g_R1[g1a], R1b = g_R1[g1b];
    float k1a = g_k1[g1a], k1b = g_k1[g1b];
    float e_r = (tid < 256) ? g_e[tid] : 0.f;
    float bf2_r = (tid < 256) ? bf2[tid] : 0.f;
    float l1g = 0.f, l1b_ = 0.f;
    if (tid < 256) { l1g = ln1g[tid]; l1b_ = ln1b[tid]; }
    float b2row = 0.f;
    int hrow = -1;
    if (tid >= 256 && tid < 256 + 16) {
        hrow = rank * 16 + (tid - 256);
        b2row = b2[hrow];
    }

    if (tid < 2)
        asm volatile("mbarrier.init.shared.b64 [%0], %1;"
                     :: "r"(a_mb + tid * 8), "r"(16) : "memory");
    if (tid < 16) redsm[tid] = 0.f;
    if (tid < 256) {
        y2s[tid] = 0.f;
        mbuf[tid] = gnn[(size_t)tid];  // m_0
    }
    __syncthreads();
    CLU_SYNC();

    float md0 = row_dot<SG>(w1ms + w * SG, mbuf, lane);
    float md1 = row_dot<SG>(w1ms + (w + 16) * SG, mbuf, lane);

    for (int t = 0; t < NSTEPS; ++t) {
        unsigned par = (unsigned)(t & 1);

        float mnext = 0.f;
        if (tid < 256)
            mnext = gnn[(size_t)((t + 1) & (NNODES - 1)) * SG + tid];

        // S1 g-dot over RAW y2; per-thread y2-stats finalize (no sync needed:
        // redsm valid since loop-end sync of previous iteration)
        float dg0 = row_dot<SG>(w1gs + w * SG, y2s, lane);
        float dg1 = row_dot<SG>(w1gs + (w + 16) * SG, y2s, lane);

        // S1 epilogue -> h1 slice
        {
            float v0, v1;
            if (t == 0) {
                v0 = md0 + b1a;
                v1 = md1 + b1b;
            } else {
                float mu2, inv2;
                stats_from_redsm(redsm, mu2, inv2);
                v0 = md0 + inv2 * (dg0 - mu2 * R1a) + k1a;
                v1 = md1 + inv2 * (dg1 - mu2 * R1b) + k1b;
            }
            if (lane == 0) {
                h1loc[w] = fmaxf(v0, 0.f);
                h1loc[w + 16] = fmaxf(v1, 0.f);
            }
        }
        __syncthreads();                                    // (A) h1loc ready

        // p1 partials: float4 h1loc loads, sequential accumulation (c order)
        {
            const float4* h4 = reinterpret_cast<const float4*>(h1loc);
            float acc = 0.f;
#pragma unroll
            for (int c4 = 0; c4 < 8; ++c4) {
                float4 hv = h4[c4];
                acc += pw[4 * c4 + 0] * hv.x;
                acc += pw[4 * c4 + 1] * hv.y;
                acc += pw[4 * c4 + 2] * hv.z;
                acc += pw[4 * c4 + 3] * hv.w;
            }
            if (tid < 256) g_ph2[par][rank * SG + tid] = acc;
            else           g_p1[rank * SG + (tid - 256)] = acc;
        }
        if (tid < 256) mbuf[tid] = mnext;
        __syncthreads();                                    // (B) stores done
        if (tid < 16) arrive_remote_rel(a_mb + 0 * 8, (unsigned)tid);

        // shadow: m-dot for t+1
        md0 = row_dot<SG>(w1ms + w * SG, mbuf, lane);
        md1 = row_dot<SG>(w1ms + (w + 16) * SG, mbuf, lane);

        bar_wait_acq(a_mb + 0 * 8, par);                    // sync 1

        // reduce y1 (+ warp stats)
        float y1v = 0.f;
        if (tid < 256) {
            float s = e_r;
#pragma unroll
            for (int k = 0; k < 16; ++k) s += g_p1[k * SG + tid];
            y1v = s;
            y1s[tid] = s;
            float sa = s, s2a = s * s;
#pragma unroll
            for (int o = 16; o; o >>= 1) {
                sa += __shfl_xor_sync(0xffffffffu, sa, o);
                s2a += __shfl_xor_sync(0xffffffffu, s2a, o);
            }
            if (lane == 0) { redsm[2 * w] = sa; redsm[2 * w + 1] = s2a; }
        }
        __syncthreads();                                    // (C) y1s + redsm

        // z = Wf1g @ y1 (raw); per-thread LN1 stats finalize
        float z[8];
#pragma unroll
        for (int i = 0; i < 8; ++i)
            z[i] = row_dot<SG>(wf1s + (w + 16 * i) * SG, y1s, lane);
        float mu1, inv1;
        stats_from_redsm(redsm, mu1, inv1);

        // ff epilogue (LN1 fold)
        if (lane == 0) {
#pragma unroll
            for (int i = 0; i < 8; ++i) {
                int r = w + 16 * i;
                ffloc[r] = fmaxf(inv1 * (z[i] - mu1 * rffs[r]) + c1s[r], 0.f);
            }
        }
        __syncthreads();                                    // (D) ffloc ready

        // p2 partials: float4 ffloc loads, sequential accumulation
        {
            int half = tid >> 8;
            const float4* fl4 = reinterpret_cast<const float4*>(ffloc + half * 64);
            float a2 = 0.f;
#pragma unroll
            for (int c4 = 0; c4 < 16; ++c4) {
                float4 fv = fl4[c4];
                a2 += wf2c[4 * c4 + 0] * fv.x;
                a2 += wf2c[4 * c4 + 1] * fv.y;
                a2 += wf2c[4 * c4 + 2] * fv.z;
                a2 += wf2c[4 * c4 + 3] * fv.w;
            }
            p2tmp[tid] = a2;
        }
        __syncthreads();                                    // (E)
        if (tid < 256) g_p2[rank * SG + tid] = p2tmp[tid] + p2tmp[tid + 256];
        __syncthreads();                                    // (F) stores done
        if (tid < 16) arrive_remote_rel(a_mb + 1 * 8, (unsigned)tid);

        // shadow: h reduce + store (double-buffered source; race-free vs t+1)
        if (hrow >= 0) {
            float s = b2row;
#pragma unroll
            for (int k = 0; k < 16; ++k) s += g_ph2[par][k * SG + hrow];
            g_h_all[(size_t)t * SG + hrow] = s;
        }

        bar_wait_acq(a_mb + 1 * 8, par);                    // sync 2

        // reduce y2 raw + warp stats
        if (tid < 256) {
            float x = (y1v - mu1) * inv1 * l1g + l1b_;
            float s = x + bf2_r;
#pragma unroll
            for (int k = 0; k < 16; ++k) s += g_p2[k * SG + tid];
            y2s[tid] = s;
            float sa = s, s2a = s * s;
#pragma unroll
            for (int o = 16; o; o >>= 1) {
                sa += __shfl_xor_sync(0xffffffffu, sa, o);
                s2a += __shfl_xor_sync(0xffffffffu, s2a, o);
            }
            if (lane == 0) { redsm[2 * w] = sa; redsm[2 * w + 1] = s2a; }
        }
        __syncthreads();                                    // (G) y2s + redsm
    }
    CLU_SYNC();
}

// ---------------------------------------------------------------------------
// Fallback (cluster size < 16): R4-proven streaming kernel, CL=8.
// ---------------------------------------------------------------------------
__global__ void __launch_bounds__(1024, 1) seq_fallback8(
    const float* __restrict__ gnn,
    const float* __restrict__ W1, const float* __restrict__ b1,
    const float* __restrict__ W2, const float* __restrict__ b2,
    const float* __restrict__ Wg, const float* __restrict__ bg,
    const float* __restrict__ Wv, const float* __restrict__ bv,
    const float* __restrict__ Wo, const float* __restrict__ bo,
    const float* __restrict__ Wf1, const float* __restrict__ bf1,
    const float* __restrict__ Wf2, const float* __restrict__ bf2,
    const float* __restrict__ ln1g, const float* __restrict__ ln1b,
    const float* __restrict__ ln2g, const float* __restrict__ ln2b) {
    constexpr int CL = 8;
    constexpr int R_H1 = H1DIM / CL, R_SG = SG / CL, R_FF = DFF / CL;
    __shared__ __align__(16) float cat[H1DIM];
    __shared__ __align__(16) float h1s[H1DIM];
    __shared__ __align__(16) float hs[SG];
    __shared__ __align__(16) float gns[SG];
    __shared__ __align__(16) float vvs[SG];
    __shared__ __align__(16) float ys[SG];
    __shared__ __align__(16) float xs[SG];
    __shared__ __align__(16) float ff1s[DFF];
    __shared__ float red[2];

    int tid = threadIdx.x, w = tid >> 5, lane = tid & 31;
    unsigned rank;
    asm("mov.u32 %0, %%cluster_ctarank;" : "=r"(rank));
    if (tid < 256) cat[256 + tid] = 0.f;
    __syncthreads();

    for (int t = 0; t < NSTEPS; ++t) {
        if (tid < 256) cat[tid] = gnn[(size_t)(t & (NNODES - 1)) * SG + tid];
        __syncthreads();
        for (int r = w; r < R_H1; r += 32) {
            int gr = rank * R_H1 + r;
            float s = row_dot<H1DIM>(W1 + (size_t)gr * H1DIM, cat, lane);
            if (lane == 0) g_bh1[gr] = fmaxf(s + b1[gr], 0.f);
        }
        CLU_SYNC();
        for (int i = tid; i < H1DIM; i += 1024) h1s[i] = g_bh1[i];
        __syncthreads();
        float* gh = g_h_all + (size_t)t * SG;
        for (int r = w; r < R_SG; r += 32) {
            int gr = rank * R_SG + r;
            float s = row_dot<H1DIM>(W2 + (size_t)gr * H1DIM, h1s, lane);
            if (lane == 0) gh[gr] = s + b2[gr];
        }
        CLU_SYNC();
        for (int i = tid; i < SG; i += 1024) hs[i] = gh[i];
        __syncthreads();
        for (int r = w; r < R_SG; r += 32) {
            int gr = rank * R_SG + r;
            float s = row_dot<SG>(Wg + (size_t)gr * SG, hs, lane);
            if (lane == 0) g_by1[gr] = s + bg[gr];
        }
        CLU_SYNC();
        for (int i = tid; i < SG; i += 1024) gns[i] = g_by1[i];
        __syncthreads();
        for (int r = w; r < R_SG; r += 32) {
            int gr = rank * R_SG + r;
            float s = row_dot<SG>(Wv + (size_t)gr * SG, gns, lane);
            if (lane == 0) g_by2[gr] = s + bv[gr];
        }
        CLU_SYNC();
        for (int i = tid; i < SG; i += 1024) vvs[i] = g_by2[i];
        __syncthreads();
        for (int r = w; r < R_SG; r += 32) {
            int gr = rank * R_SG + r;
            float s = row_dot<SG>(Wo + (size_t)gr * SG, vvs, lane);
            if (lane == 0) g_by1[gr] = gns[gr] + (s + bo[gr]);
        }
        CLU_SYNC();
        for (int i = tid; i < SG; i += 1024) ys[i] = g_by1[i];
        __syncthreads();
        layernorm256(ys, xs, ln1g, ln1b, tid, red);
        for (int r = w; r < R_FF; r += 32) {
            int gr = rank * R_FF + r;
            float s = row_dot<SG>(Wf1 + (size_t)gr * SG, xs, lane);
            if (lane == 0) g_bff[gr] = fmaxf(s + bf1[gr], 0.f);
        }
        CLU_SYNC();
        for (int i = tid; i < DFF; i += 1024) ff1s[i] = g_bff[i];
        __syncthreads();
        for (int r = w; r < R_SG; r += 32) {
            int gr = rank * R_SG + r;
            float s = row_dot<DFF>(Wf2 + (size_t)gr * DFF, ff1s, lane);
            if (lane == 0) g_by2[gr] = xs[gr] + (s + bf2[gr]);
        }
        CLU_SYNC();
        for (int i = tid; i < SG; i += 1024) ys[i] = g_by2[i];
        __syncthreads();
        layernorm256(ys, cat + 256, ln2g, ln2b, tid, red);
    }
}

// ---------------------------------------------------------------------------
// Sampler: T=16 timesteps per block (halved Wr traffic), bit-exact probs path.
// ---------------------------------------------------------------------------
#define SAMP_T 16
#define SAMP_THREADS 512
#define SAMP_SMEM ((SAMP_T * SG + SAMP_T * NROW) * 4)

__global__ void __launch_bounds__(SAMP_THREADS) sample_kernel16(
    const float* __restrict__ u,
    const float* __restrict__ Wr, const float* __restrict__ br,
    float* __restrict__ out) {
    extern __shared__ __align__(16) float sm[];
    float* hsm = sm;
    float* probs = sm + SAMP_T * SG;
    __shared__ int cnt[SAMP_T][4];
    __shared__ int sel[SAMP_T];

    int tb = blockIdx.x * SAMP_T;
    int tid = threadIdx.x, w = tid >> 5, lane = tid & 31;

    for (int i = tid; i < SAMP_T * SG; i += SAMP_THREADS)
        hsm[i] = g_h_all[(size_t)tb * SG + i];
    if (tid < SAMP_T * 4) cnt[tid >> 2][tid & 3] = 0;
    __syncthreads();

    for (int r = w; r < NROW; r += 16) {
        const float* Wrow = Wr + (size_t)r * SG;
        float brv = br[r];
#pragma unroll
        for (int j = 0; j < SAMP_T; ++j) {
            float s = row_dot<SG>(Wrow, hsm + j * SG, lane);
            if (lane == 0) {
                float z = s + brv;
                float p;
                if (z >= 0.f) {
                    p = 1.f / (1.f + expf(-z));
                } else {
                    float e = expf(z);
                    p = e / (1.f + e);
                }
                probs[j * NROW + r] = p;
            }
        }
    }
    __syncthreads();

#pragma unroll
    for (int j = 0; j < SAMP_T; ++j) {
        const float* __restrict__ ut = u + (size_t)(tb + j) * 4 * NROW;
        int c[4] = {0, 0, 0, 0};
#pragma unroll
        for (int k = 0; k < 4; ++k)
#pragma unroll
            for (int i = 0; i < NROW / SAMP_THREADS; ++i) {
                int n = tid + SAMP_THREADS * i;
                c[k] += (ut[k * NROW + n] < probs[j * NROW + n]) ? 1 : 0;
            }
#pragma unroll
        for (int k = 0; k < 4; ++k) {
            int s = c[k];
#pragma unroll
            for (int o = 16; o; o >>= 1) s += __shfl_xor_sync(0xffffffffu, s, o);
            if (lane == 0) atomicAdd(&cnt[j][k], s);
        }
    }
    __syncthreads();

    if (tid < SAMP_T) {
        int idx = 0;
        for (int k = 3; k >= 0; --k) {
            int ck = cnt[tid][k];
            bool valid = (ck == 0) || (ck >= 2 && ck <= 6);
            if (valid) idx = k;
        }
        sel[tid] = idx;
    }
    __syncthreads();

#pragma unroll
    for (int j = 0; j < SAMP_T; ++j) {
        const float* __restrict__ ut = u + (size_t)(tb + j) * 4 * NROW;
        int idx = sel[j];
#pragma unroll
        for (int i = 0; i < NROW / SAMP_THREADS; ++i) {
            int n = tid + SAMP_THREADS * i;
            out[(size_t)(tb + j) * NROW + n] =
                (ut[idx * NROW + n] < probs[j * NROW + n]) ? 1.f : 0.f;
        }
    }
}

extern "C" void kernel_launch(void* const* d_in, const int* in_sizes, int n_in,
                              void* d_out, int out_size) {
    (void)in_sizes; (void)n_in; (void)out_size;
    const float* gnn  = (const float*)d_in[0];
    const float* u    = (const float*)d_in[2];
    const float* W1   = (const float*)d_in[3];
    const float* b1   = (const float*)d_in[4];
    const float* W2   = (const float*)d_in[5];
    const float* b2   = (const float*)d_in[6];
    const float* Wr   = (const float*)d_in[7];
    const float* br   = (const float*)d_in[8];
    const float* Wg   = (const float*)d_in[9];
    const float* bg   = (const float*)d_in[10];
    const float* Wv   = (const float*)d_in[11];
    const float* bv   = (const float*)d_in[12];
    const float* Wo   = (const float*)d_in[13];
    const float* bo   = (const float*)d_in[14];
    const float* Wf1  = (const float*)d_in[15];
    const float* bf1  = (const float*)d_in[16];
    const float* Wf2  = (const float*)d_in[17];
    const float* bf2  = (const float*)d_in[18];
    const float* ln1g = (const float*)d_in[19];
    const float* ln1b = (const float*)d_in[20];
    const float* ln2g = (const float*)d_in[21];
    const float* ln2b = (const float*)d_in[22];

    // folds (deterministic, every call)
    fold1<<<SG, SG>>>(Wo, Wv);
    fold2<<<SG, SG>>>(Wg, bg, Wo, bv, bo);
    fold3<<<SG, H1DIM>>>(W2, b2);
    fold4<<<DFF, SG>>>(Wf1, bf1, ln1g, ln1b);
    fold5<<<H1DIM, SG>>>(W1, b1, ln2g, ln2b);

    cudaFuncSetAttribute(seq7_kernel,
                         cudaFuncAttributeMaxDynamicSharedMemorySize, SEQ7_SMEM_BYTES);
    cudaFuncSetAttribute(seq7_kernel,
                         cudaFuncAttributeNonPortableClusterSizeAllowed, 1);

    cudaError_t e = cudaErrorUnknown;
    {
        cudaLaunchConfig_t cfg = {};
        cfg.gridDim = dim3(16, 1, 1);
        cfg.blockDim = dim3(512, 1, 1);
        cfg.dynamicSmemBytes = SEQ7_SMEM_BYTES;
        cfg.stream = 0;
        cudaLaunchAttribute at[1];
        at[0].id = cudaLaunchAttributeClusterDimension;
        at[0].val.clusterDim.x = 16;
        at[0].val.clusterDim.y = 1;
        at[0].val.clusterDim.z = 1;
        cfg.attrs = at;
        cfg.numAttrs = 1;
        e = cudaLaunchKernelEx(&cfg, seq7_kernel,
                               gnn, W1, b1, W2, b2, Wf2, bf2, ln1g, ln1b);
    }
    if (e != cudaSuccess) {
        cudaLaunchConfig_t cfg = {};
        cfg.gridDim = dim3(8, 1, 1);
        cfg.blockDim = dim3(1024, 1, 1);
        cfg.dynamicSmemBytes = 0;
        cfg.stream = 0;
        cudaLaunchAttribute at[1];
        at[0].id = cudaLaunchAttributeClusterDimension;
        at[0].val.clusterDim.x = 8;
        at[0].val.clusterDim.y = 1;
        at[0].val.clusterDim.z = 1;
        cfg.attrs = at;
        cfg.numAttrs = 1;
        cudaLaunchKernelEx(&cfg, seq_fallback8,
                           gnn, W1, b1, W2, b2, Wg, bg, Wv, bv, Wo, bo,
                           Wf1, bf1, Wf2, bf2, ln1g, ln1b, ln2g, ln2b);
    }

    cudaFuncSetAttribute(sample_kernel16,
                         cudaFuncAttributeMaxDynamicSharedMemorySize, SAMP_SMEM);
    sample_kernel16<<<NSTEPS / SAMP_T, SAMP_THREADS, SAMP_SMEM>>>(
        u, Wr, br, (float*)d_out);
}